// round 15
// baseline (speedup 1.0000x reference)
#include <cuda_runtime.h>
#include <math.h>

#define N_MOL  2048
#define P_PRO  2048
#define HID    64
#define HEADS  16
#define NGRAPH 64
#define NB     512
#define NBLK   128          // 128 blocks x 1024 threads; blocks 0..15 are consumers
#define NTHR   1024
#define AROWS  32           // rows per block in Phase A

// ---- global scratch (no allocation allowed) ----
__device__ float2 g_mol2[HEADS][N_MOL];   // (a_mol, exp(a_mol))
__device__ float2 g_pro2[HEADS][P_PRO];   // (a_pro, exp(a_pro))
__device__ float  g_ys[NGRAPH * HEADS];
__device__ unsigned g_mnU[HEADS] = {      // order-encoded per-head min (consumers reset)
    0xFFFFFFFFu,0xFFFFFFFFu,0xFFFFFFFFu,0xFFFFFFFFu,0xFFFFFFFFu,0xFFFFFFFFu,
    0xFFFFFFFFu,0xFFFFFFFFu,0xFFFFFFFFu,0xFFFFFFFFu,0xFFFFFFFFu,0xFFFFFFFFu,
    0xFFFFFFFFu,0xFFFFFFFFu,0xFFFFFFFFu,0xFFFFFFFFu};
__device__ unsigned g_mxU[HEADS];         // zero-init = encoded far-below-min
__device__ int    g_gen;                  // barrier generation (monotone)
__device__ int    g_cnt1[16];             // leaf arrival counters (self-reset)
__device__ int    g_count;                // root arrival counter (self-resets)
__device__ int    g_done;                 // consumer completions (self-resets)

struct SA {                                // Phase A: 14,656 B
    float rows[AROWS * HID];               // 8192
    float Wst[HEADS][68];                  // 4352  transposed weights, padded rows
    float trans[HEADS][AROWS + 1];         // 2112
};
struct SB {                                // Phase B (~34KB; VE array eliminated)
    union { int bs[N_MOL];   float qam[N_MOL]; };  // bs pre-barrier -> qam post
    union { float dead[N_MOL]; float qem[N_MOL]; };
    int    segStart[NGRAPH + 1];           // pre-barrier segment boundaries
    int    hist[NB];                       // per-bin count   (atomic accum)
    float  sumEb[NB];                      // per-bin sum e^v (atomic accum)
    float  sumVb[NB];                      // per-bin sum v   (atomic accum)
    float  sumV2b[NB];                     // per-bin sum v^2 (atomic accum)
    int    binStart[NB + 1];
    float  prefExp[NB];                    // sum e^v over bins < k
    float  sufVal[NB + 1];                 // sum v over bins >= k
    float  w1s[2 * HEADS * HEADS];         // W1 preload (block 0)
    int    iwarp[16];
    double dE[16], dV[16];
    float  mnv, mxv, invv, totE, totV;
    int    flag;
};
union SmemU { SA a; SB b; };

// order-preserving float<->uint encoding (atomicMin/Max-compatible)
__device__ __forceinline__ unsigned encF(float f) {
    unsigned b = __float_as_uint(f);
    return (b & 0x80000000u) ? ~b : (b | 0x80000000u);
}
__device__ __forceinline__ float decF(unsigned u) {
    return (u & 0x80000000u) ? __uint_as_float(u & 0x7FFFFFFFu)
                             : __uint_as_float(~u);
}
__device__ __forceinline__ int bin_of(float v, float mn, float inv) {
    // single shared helper => identical rounding for elements and queries
    int b = (int)(__fmul_rn(__fsub_rn(v, mn), inv));
    return b < 0 ? 0 : (b > NB - 1 ? NB - 1 : b);
}

__global__ __launch_bounds__(NTHR, 1)
void fused_kernel(const float* __restrict__ mol,
                  const float* __restrict__ pro,
                  const float* __restrict__ Wmu,
                  const float* __restrict__ bmu,
                  const float* __restrict__ W1,
                  const float* __restrict__ b1,
                  const float* __restrict__ W2,
                  const float* __restrict__ b2,
                  const int*   __restrict__ batch32,
                  float* __restrict__ out) {
    __shared__ SmemU sm;
    int tid  = threadIdx.x;
    int lane = tid & 31;
    int wrp  = tid >> 5;
    int bid  = blockIdx.x;

    // ===== Phase A: block bid projects 32 rows (all heads) =====
    bool is_mol  = bid < 64;
    int  rowbase = (bid & 63) * AROWS;
    const float* srcbase = is_mol ? mol : pro;
    {   // transposed weight fill: coalesced LDG, one STS per thread
        int k = tid >> 4, hh = tid & 15;
        sm.a.Wst[hh][k] = Wmu[(is_mol ? 0 : 1024) + tid];
    }
    if (tid < AROWS * HID / 4)
        ((float4*)sm.a.rows)[tid] = ((const float4*)(srcbase + rowbase * HID))[tid];
    __syncthreads();
    if (tid < AROWS * HEADS) {   // 512 products: warp = 2 rows x 16 heads (wt dedup)
        int r = tid >> 4, h = tid & 15;
        const float4* rp = (const float4*)&sm.a.rows[r * HID];
        const float4* wp = (const float4*)&sm.a.Wst[h][0];
        float acc = is_mol ? bmu[h] : 0.0f;
#pragma unroll
        for (int q = 0; q < 16; q++) {
            float4 rv = rp[q];
            float4 wv = wp[q];
            acc += rv.x * wv.x; acc += rv.y * wv.y;
            acc += rv.z * wv.z; acc += rv.w * wv.w;
        }
        sm.a.trans[h][r] = acc;
    }
    __syncthreads();
    if (tid < AROWS * HEADS) {   // writeout: warp = one head x 32 rows, coalesced
        int h2 = tid >> 5, r2 = tid & 31;
        float a = sm.a.trans[h2][r2];
        float2* dst = is_mol ? g_mol2[h2] : g_pro2[h2];
        dst[rowbase + r2] = make_float2(a, __expf(a));
        if (!is_mol) {
            float wmn = a, wmx = a;
#pragma unroll
            for (int o = 16; o > 0; o >>= 1) {
                wmn = fminf(wmn, __shfl_xor_sync(0xffffffffu, wmn, o));
                wmx = fmaxf(wmx, __shfl_xor_sync(0xffffffffu, wmx, o));
            }
            if (lane == 0) {
                atomicMin(&g_mnU[h2], encF(wmn));
                atomicMax(&g_mxU[h2], encF(wmx));
            }
        }
    }
    __threadfence();
    __syncthreads();

    // ===== two-level barrier arrival (16 leaves x 8, root x 16) =====
    int my = 0;
    if (tid == 0) {
        my = *(volatile int*)&g_gen;
        if (atomicAdd(&g_cnt1[bid >> 3], 1) == 7) {
            atomicExch(&g_cnt1[bid >> 3], 0);
            if (atomicAdd(&g_count, 1) == 15) {
                atomicExch(&g_count, 0);
                __threadfence();
                atomicAdd(&g_gen, 1);
            }
        }
    }
    if (bid >= HEADS) return;

    // ===== consumer prep, overlapped with other blocks' Phase A =====
    int h = bid;
    for (int i = tid; i < N_MOL; i += NTHR) sm.b.bs[i] = batch32[i];
    if (tid < NB) {
        sm.b.hist[tid]  = 0;
        sm.b.sumEb[tid] = 0.0f; sm.b.sumVb[tid] = 0.0f; sm.b.sumV2b[tid] = 0.0f;
    }
    if (tid == 0) sm.b.flag = 0;
    __syncthreads();
    // int64 detection: sorted int32 word stream is monotone; int64's is not
    for (int i = tid; i < N_MOL - 1; i += NTHR)
        if (sm.b.bs[i] > sm.b.bs[i + 1]) sm.b.flag = 1;
    __syncthreads();
    if (sm.b.flag) {   // int64: low word of each element
        for (int i = tid; i < N_MOL; i += NTHR) sm.b.bs[i] = batch32[2 * i];
    }
    __syncthreads();
    // segment boundaries via binary search, OFF the post-barrier critical path
    if (tid <= NGRAPH) {
        int lo = 0, hi = N_MOL;
        while (lo < hi) { int m = (lo + hi) >> 1; if (sm.b.bs[m] < tid) lo = m + 1; else hi = m; }
        sm.b.segStart[tid] = lo;
    }
    __syncthreads();   // bs reads done before qam/qem overwrite below

    // ===== spin on barrier; tid0 also fetches producer min/max =====
    if (tid == 0) {
        while (*(volatile int*)&g_gen == my) {}
        __threadfence();
        float a = decF(*(volatile unsigned*)&g_mnU[h]);
        float b = decF(*(volatile unsigned*)&g_mxU[h]);
        g_mnU[h] = 0xFFFFFFFFu;           // reset for next replay
        g_mxU[h] = 0u;
        sm.b.mnv = a; sm.b.mxv = b;
        sm.b.invv = (b > a) ? (float)NB / (b - a) : 0.0f;
    }
    __syncthreads();
    float mnv = sm.b.mnv, mxv = sm.b.mxv, inv = sm.b.invv;

    // ===== Phase B: all global loads up front; mol2 staged to smem =====
    float2 pA = g_pro2[h][tid];
    float2 pB = g_pro2[h][tid + 1024];
    {
        float2 qA = g_mol2[h][tid];
        float2 qB = g_mol2[h][tid + 1024];
        sm.b.qam[tid] = qA.x;        sm.b.qem[tid] = qA.y;
        sm.b.qam[tid + 1024] = qB.x; sm.b.qem[tid + 1024] = qB.y;
    }

    // direct moment accumulation (replaces hist+scatter+rescan)
    {
        int bA = bin_of(pA.x, mnv, inv), bB = bin_of(pB.x, mnv, inv);
        atomicAdd(&sm.b.hist[bA], 1);
        atomicAdd(&sm.b.sumEb[bA],  pA.y);
        atomicAdd(&sm.b.sumVb[bA],  pA.x);
        atomicAdd(&sm.b.sumV2b[bA], pA.x * pA.x);
        atomicAdd(&sm.b.hist[bB], 1);
        atomicAdd(&sm.b.sumEb[bB],  pB.y);
        atomicAdd(&sm.b.sumVb[bB],  pB.x);
        atomicAdd(&sm.b.sumV2b[bB], pB.x * pB.x);
    }
    __syncthreads();

    // ===== joint scan: counts (int) + sumE/sumV (double), one shfl ladder =====
    {
        int c = 0; double se = 0.0, sv = 0.0;
        if (tid < NB) {
            c  = sm.b.hist[tid];
            se = (double)sm.b.sumEb[tid];
            sv = (double)sm.b.sumVb[tid];
        }
        int ic = c; double ise = se, isv = sv;
        if (tid < NB) {
#pragma unroll
            for (int o = 1; o < 32; o <<= 1) {
                int    tc = __shfl_up_sync(0xffffffffu, ic, o);
                double te = __shfl_up_sync(0xffffffffu, ise, o);
                double tv = __shfl_up_sync(0xffffffffu, isv, o);
                if (lane >= o) { ic += tc; ise += te; isv += tv; }
            }
            if (lane == 31) { sm.b.iwarp[wrp] = ic; sm.b.dE[wrp] = ise; sm.b.dV[wrp] = isv; }
        }
        __syncthreads();
        if (tid < 16) {
            int pc = sm.b.iwarp[tid];
            double pe = sm.b.dE[tid], pv = sm.b.dV[tid];
#pragma unroll
            for (int o = 1; o < 16; o <<= 1) {
                int    tc = __shfl_up_sync(0xffffu, pc, o);
                double te = __shfl_up_sync(0xffffu, pe, o);
                double tv = __shfl_up_sync(0xffffu, pv, o);
                if (tid >= o) { pc += tc; pe += te; pv += tv; }
            }
            sm.b.iwarp[tid] = pc; sm.b.dE[tid] = pe; sm.b.dV[tid] = pv;
        }
        __syncthreads();
        if (tid < NB) {
            int    offC = (wrp > 0) ? sm.b.iwarp[wrp - 1] : 0;
            double offE = (wrp > 0) ? sm.b.dE[wrp - 1] : 0.0;
            double offV = (wrp > 0) ? sm.b.dV[wrp - 1] : 0.0;
            double inclE = ise + offE, inclV = isv + offV;
            double totalV = sm.b.dV[15];
            sm.b.binStart[tid + 1] = ic + offC;
            sm.b.prefExp[tid] = (float)(inclE - se);
            sm.b.sufVal[tid]  = (float)(totalV - (inclV - sv));
            if (tid == 0) {
                sm.b.binStart[0] = 0;
                sm.b.sufVal[NB]  = 0.0f;
                sm.b.totE = (float)sm.b.dE[15];
                sm.b.totV = (float)totalV;
            }
        }
    }
    __syncthreads();
    float totE = sm.b.totE, totV = sm.b.totV;

    // ===== fused queries + segment sum (16 threads per graph) =====
    {
        int gb = tid >> 4, q = tid & 15;
        int s = sm.b.segStart[gb], e = sm.b.segStart[gb + 1];
        float p = 0.0f;
        for (int n = s + q; n < e; n += 16) {
            float am = sm.b.qam[n], eam = sm.b.qem[n];
            float t = -am;
            float acc;
            if (t >= mxv) {                     // all elements on exp side (exact)
                acc = eam * totE;
            } else if (t < mnv) {               // all elements on linear side (exact)
                acc = fmaf((float)P_PRO, am + 1.0f, totV);
            } else {
                int b  = bin_of(t, mnv, inv);
                int e0 = sm.b.binStart[b + 1];
                float cb  = (float)sm.b.hist[b];
                float sV  = sm.b.sumVb[b];
                float sV2 = sm.b.sumV2b[b];
                float lin = am + 1.0f;
                // bins<b exact exp side; bins>b exact linear side; boundary bin:
                // sum of 1 + x + x^2/4 with x = am+v, |x| <= ~2*binwidth
                acc = eam * sm.b.prefExp[b] + sm.b.sufVal[b + 1]
                    + (float)(P_PRO - e0) * lin
                    + cb * lin + sV
                    + 0.25f * fmaf(cb, am * am, fmaf(2.0f * am, sV, sV2));
            }
            p += acc;
        }
#pragma unroll
        for (int o = 8; o > 0; o >>= 1) p += __shfl_xor_sync(0xffffffffu, p, o);
        if (q == 0) g_ys[gb * HEADS + h] = p * 0.001f;
    }
    __threadfence();
    __syncthreads();
    if (bid != 0) {
        if (tid == 0) atomicAdd(&g_done, 1);
        return;
    }

    // ===== final MLP (block 0): preload W1, then wait, then compute =====
    if (tid < 2 * HEADS * HEADS) sm.b.w1s[tid] = W1[tid];
    if (tid == 0) {
        while (atomicAdd(&g_done, 0) < HEADS - 1) {}
        atomicExch(&g_done, 0);
        __threadfence();
    }
    __syncthreads();
    float* ysF = sm.b.qam;    // dead; reuse for 64x16 ys
    if (tid < NGRAPH * HEADS) ysF[tid] = __ldcg(&g_ys[tid]);
    __syncthreads();
#pragma unroll
    for (int pass = 0; pass < 2; pass++) {
        int gb = (tid >> 5) + pass * 32;     // graph
        int j  = tid & 31;                   // hidden unit
        float a = b1[j];
#pragma unroll
        for (int hh = 0; hh < HEADS; hh++)
            a += ysF[gb * HEADS + hh] * sm.b.w1s[hh * (2 * HEADS) + j];
        float el = (a > 0.0f) ? a : (expf(a) - 1.0f);
        float c = el * W2[j];
#pragma unroll
        for (int o = 16; o > 0; o >>= 1) c += __shfl_xor_sync(0xffffffffu, c, o);
        if (j == 0) out[gb] = c + b2[0];
    }
}

// Inputs (metadata order):
// 0 mol_feats [2048,64] f32   1 fused_feats [2048,64] f32
// 2 Wmu [128,16] f32          3 bmu [16] f32
// 4 W1 [16,32] f32            5 b1 [32] f32
// 6 W2 [32,1] f32             7 b2 [1] f32
// 8 mol_batch [2048] int64-or-int32   9 num_graphs (static B=64)
extern "C" void kernel_launch(void* const* d_in, const int* in_sizes, int n_in,
                              void* d_out, int out_size) {
    fused_kernel<<<NBLK, NTHR>>>(
        (const float*)d_in[0], (const float*)d_in[1],
        (const float*)d_in[2], (const float*)d_in[3],
        (const float*)d_in[4], (const float*)d_in[5],
        (const float*)d_in[6], (const float*)d_in[7],
        (const int*)d_in[8], (float*)d_out);
}

// round 16
// speedup vs baseline: 1.0935x; 1.0935x over previous
#include <cuda_runtime.h>
#include <math.h>

#define N_MOL  2048
#define P_PRO  2048
#define HID    64
#define HEADS  16
#define NGRAPH 64
#define NB     512
#define NBLK   128          // 128 blocks x 1024 threads; blocks 0..15 are consumers
#define NTHR   1024
#define AROWS  32           // rows per block in Phase A

// ---- global scratch (no allocation allowed) ----
__device__ float2 g_mol2[HEADS][N_MOL];   // (a_mol, exp(a_mol))
__device__ float2 g_pro2[HEADS][P_PRO];   // (a_pro, exp(a_pro))
__device__ float  g_ys[NGRAPH * HEADS];
__device__ unsigned g_mnU[HEADS] = {      // order-encoded per-head min (consumers reset)
    0xFFFFFFFFu,0xFFFFFFFFu,0xFFFFFFFFu,0xFFFFFFFFu,0xFFFFFFFFu,0xFFFFFFFFu,
    0xFFFFFFFFu,0xFFFFFFFFu,0xFFFFFFFFu,0xFFFFFFFFu,0xFFFFFFFFu,0xFFFFFFFFu,
    0xFFFFFFFFu,0xFFFFFFFFu,0xFFFFFFFFu,0xFFFFFFFFu};
__device__ unsigned g_mxU[HEADS];         // zero-init = encoded far-below-min
__device__ int    g_gen;                  // barrier generation (monotone)
__device__ int    g_cnt1[16];             // leaf arrival counters (self-reset)
__device__ int    g_count;                // root arrival counter (self-resets)
__device__ int    g_done;                 // consumer completions (self-resets)

struct SA {                                // Phase A: 14,656 B
    float rows[AROWS * HID];               // 8192
    float Wst[HEADS][68];                  // 4352  transposed weights, padded rows
    float trans[HEADS][AROWS + 1];         // 2112
};
struct SB {                                // Phase B
    float2 VE[P_PRO];                      // 16384  (post-barrier)
    union { int bs[N_MOL];   float qam[N_MOL]; };  // bs pre-barrier -> qam post
    union { float dead[N_MOL]; float qem[N_MOL]; };
    int    segStart[NGRAPH + 1];           // pre-barrier segment boundaries
    int    hist[NB];                       // pre-barrier zeroed
    int    cnt[NB];                        // pre-barrier zeroed
    int    binStart[NB + 1];
    float  prefExp[NB];                    // sum e^v over bins < k
    float  sufVal[NB + 1];                 // sum v over bins >= k
    float  sumVb[NB];                      // per-bin sum of values
    float  sumV2b[NB];                     // per-bin sum of squares
    float  w1s[2 * HEADS * HEADS];         // W1 preload (all consumers, pre-barrier)
    int    iwarp[16];
    double dE[16], dV[16];
    float  mnv, mxv, invv, totE, totV;
    int    flag;
    int    amLast;
};
union SmemU { SA a; SB b; };

// order-preserving float<->uint encoding (atomicMin/Max-compatible)
__device__ __forceinline__ unsigned encF(float f) {
    unsigned b = __float_as_uint(f);
    return (b & 0x80000000u) ? ~b : (b | 0x80000000u);
}
__device__ __forceinline__ float decF(unsigned u) {
    return (u & 0x80000000u) ? __uint_as_float(u & 0x7FFFFFFFu)
                             : __uint_as_float(~u);
}
__device__ __forceinline__ int bin_of(float v, float mn, float inv) {
    // single shared helper => identical rounding for elements and queries
    int b = (int)(__fmul_rn(__fsub_rn(v, mn), inv));
    return b < 0 ? 0 : (b > NB - 1 ? NB - 1 : b);
}

__global__ __launch_bounds__(NTHR, 1)
void fused_kernel(const float* __restrict__ mol,
                  const float* __restrict__ pro,
                  const float* __restrict__ Wmu,
                  const float* __restrict__ bmu,
                  const float* __restrict__ W1,
                  const float* __restrict__ b1,
                  const float* __restrict__ W2,
                  const float* __restrict__ b2,
                  const int*   __restrict__ batch32,
                  float* __restrict__ out) {
    __shared__ SmemU sm;
    int tid  = threadIdx.x;
    int lane = tid & 31;
    int wrp  = tid >> 5;
    int bid  = blockIdx.x;

    // ===== Phase A: block bid projects 32 rows (all heads) =====
    bool is_mol  = bid < 64;
    int  rowbase = (bid & 63) * AROWS;
    const float* srcbase = is_mol ? mol : pro;
    {   // transposed weight fill: coalesced LDG, one STS per thread
        int k = tid >> 4, hh = tid & 15;
        sm.a.Wst[hh][k] = Wmu[(is_mol ? 0 : 1024) + tid];
    }
    if (tid < AROWS * HID / 4)
        ((float4*)sm.a.rows)[tid] = ((const float4*)(srcbase + rowbase * HID))[tid];
    __syncthreads();
    if (tid < AROWS * HEADS) {   // 512 products: warp = 2 rows x 16 heads (wt dedup)
        int r = tid >> 4, h = tid & 15;
        const float4* rp = (const float4*)&sm.a.rows[r * HID];
        const float4* wp = (const float4*)&sm.a.Wst[h][0];
        float acc = is_mol ? bmu[h] : 0.0f;
#pragma unroll
        for (int q = 0; q < 16; q++) {
            float4 rv = rp[q];
            float4 wv = wp[q];
            acc += rv.x * wv.x; acc += rv.y * wv.y;
            acc += rv.z * wv.z; acc += rv.w * wv.w;
        }
        sm.a.trans[h][r] = acc;
    }
    __syncthreads();
    if (tid < AROWS * HEADS) {   // writeout: warp = one head x 32 rows, coalesced
        int h2 = tid >> 5, r2 = tid & 31;
        float a = sm.a.trans[h2][r2];
        float2* dst = is_mol ? g_mol2[h2] : g_pro2[h2];
        dst[rowbase + r2] = make_float2(a, __expf(a));
        if (!is_mol) {
            float wmn = a, wmx = a;
#pragma unroll
            for (int o = 16; o > 0; o >>= 1) {
                wmn = fminf(wmn, __shfl_xor_sync(0xffffffffu, wmn, o));
                wmx = fmaxf(wmx, __shfl_xor_sync(0xffffffffu, wmx, o));
            }
            if (lane == 0) {
                atomicMin(&g_mnU[h2], encF(wmn));
                atomicMax(&g_mxU[h2], encF(wmx));
            }
        }
    }
    __threadfence();
    __syncthreads();

    // ===== two-level barrier arrival (16 leaves x 8, root x 16) =====
    int my = 0;
    if (tid == 0) {
        my = *(volatile int*)&g_gen;
        if (atomicAdd(&g_cnt1[bid >> 3], 1) == 7) {
            atomicExch(&g_cnt1[bid >> 3], 0);
            if (atomicAdd(&g_count, 1) == 15) {
                atomicExch(&g_count, 0);
                __threadfence();
                atomicAdd(&g_gen, 1);
            }
        }
    }
    if (bid >= HEADS) return;

    // ===== consumer prep, overlapped with other blocks' Phase A =====
    int h = bid;
    for (int i = tid; i < N_MOL; i += NTHR) sm.b.bs[i] = batch32[i];
    if (tid < NB) { sm.b.hist[tid] = 0; sm.b.cnt[tid] = 0; }
    if (tid < 2 * HEADS * HEADS) sm.b.w1s[tid] = W1[tid];   // MLP weights (any block may finish last)
    if (tid == 0) sm.b.flag = 0;
    __syncthreads();
    // int64 detection: sorted int32 word stream is monotone; int64's is not
    for (int i = tid; i < N_MOL - 1; i += NTHR)
        if (sm.b.bs[i] > sm.b.bs[i + 1]) sm.b.flag = 1;
    __syncthreads();
    if (sm.b.flag) {   // int64: low word of each element
        for (int i = tid; i < N_MOL; i += NTHR) sm.b.bs[i] = batch32[2 * i];
    }
    __syncthreads();
    // segment boundaries via binary search, OFF the post-barrier critical path
    if (tid <= NGRAPH) {
        int lo = 0, hi = N_MOL;
        while (lo < hi) { int m = (lo + hi) >> 1; if (sm.b.bs[m] < tid) lo = m + 1; else hi = m; }
        sm.b.segStart[tid] = lo;
    }
    __syncthreads();   // bs reads done before qam/qem overwrite below

    // ===== spin on barrier; tid0 also fetches producer min/max =====
    if (tid == 0) {
        while (*(volatile int*)&g_gen == my) {}
        __threadfence();
        float a = decF(*(volatile unsigned*)&g_mnU[h]);
        float b = decF(*(volatile unsigned*)&g_mxU[h]);
        g_mnU[h] = 0xFFFFFFFFu;           // reset for next replay
        g_mxU[h] = 0u;
        sm.b.mnv = a; sm.b.mxv = b;
        sm.b.invv = (b > a) ? (float)NB / (b - a) : 0.0f;
    }
    __syncthreads();
    float mnv = sm.b.mnv, mxv = sm.b.mxv, inv = sm.b.invv;

    // ===== Phase B: all global loads up front; mol2 staged to smem =====
    float2 pA = g_pro2[h][tid];
    float2 pB = g_pro2[h][tid + 1024];
    {
        float2 qA = g_mol2[h][tid];
        float2 qB = g_mol2[h][tid + 1024];
        sm.b.qam[tid] = qA.x;        sm.b.qem[tid] = qA.y;
        sm.b.qam[tid + 1024] = qB.x; sm.b.qem[tid + 1024] = qB.y;
    }

    // histogram straight from registers
    int bA = bin_of(pA.x, mnv, inv), bB = bin_of(pB.x, mnv, inv);
    atomicAdd(&sm.b.hist[bA], 1);
    atomicAdd(&sm.b.hist[bB], 1);
    __syncthreads();

    // exclusive scan of hist -> binStart (512 entries, 16 warps, shfl hierarchy)
    int myCnt = 0, myIncl = 0;
    {
        int s = 0;
        if (tid < NB) {
            myCnt = sm.b.hist[tid];
            s = myCnt;
#pragma unroll
            for (int o = 1; o < 32; o <<= 1) {
                int t = __shfl_up_sync(0xffffffffu, s, o);
                if (lane >= o) s += t;
            }
            if (lane == 31) sm.b.iwarp[wrp] = s;
        }
        __syncthreads();
        if (tid < 16) {
            int p = sm.b.iwarp[tid];
#pragma unroll
            for (int o = 1; o < 16; o <<= 1) {
                int t = __shfl_up_sync(0xffffu, p, o);
                if (tid >= o) p += t;
            }
            sm.b.iwarp[tid] = p;
        }
        __syncthreads();
        if (tid < NB) {
            myIncl = s + (wrp > 0 ? sm.b.iwarp[wrp - 1] : 0);
            sm.b.binStart[tid + 1] = myIncl;
            if (tid == 0) sm.b.binStart[0] = 0;
        }
    }
    __syncthreads();

    // scatter from registers
    {
        int pos = sm.b.binStart[bA] + atomicAdd(&sm.b.cnt[bA], 1);
        sm.b.VE[pos] = pA;
        pos = sm.b.binStart[bB] + atomicAdd(&sm.b.cnt[bB], 1);
        sm.b.VE[pos] = pB;
    }
    __syncthreads();

    // per-bin moments + joint double scan (prefExp exclusive / sufVal suffix)
    {
        double se = 0.0, sv = 0.0;
        if (tid < NB) {
            int s0 = myIncl - myCnt, e0 = myIncl;
            float fe = 0.0f, fv = 0.0f, fv2 = 0.0f;
            for (int i = s0; i < e0; i++) {
                float2 ve = sm.b.VE[i];
                fe += ve.y; fv += ve.x; fv2 += ve.x * ve.x;
            }
            sm.b.sumVb[tid]  = fv;
            sm.b.sumV2b[tid] = fv2;
            se = (double)fe; sv = (double)fv;
        }
        double ise = se, isv = sv;
        if (tid < NB) {
#pragma unroll
            for (int o = 1; o < 32; o <<= 1) {
                double te = __shfl_up_sync(0xffffffffu, ise, o);
                double tv = __shfl_up_sync(0xffffffffu, isv, o);
                if (lane >= o) { ise += te; isv += tv; }
            }
            if (lane == 31) { sm.b.dE[wrp] = ise; sm.b.dV[wrp] = isv; }
        }
        __syncthreads();
        if (tid < 16) {
            double pe = sm.b.dE[tid], pv = sm.b.dV[tid];
#pragma unroll
            for (int o = 1; o < 16; o <<= 1) {
                double te = __shfl_up_sync(0xffffu, pe, o);
                double tv = __shfl_up_sync(0xffffu, pv, o);
                if (tid >= o) { pe += te; pv += tv; }
            }
            sm.b.dE[tid] = pe; sm.b.dV[tid] = pv;
        }
        __syncthreads();
        if (tid < NB) {
            double offE = (wrp > 0) ? sm.b.dE[wrp - 1] : 0.0;
            double offV = (wrp > 0) ? sm.b.dV[wrp - 1] : 0.0;
            double inclE = ise + offE, inclV = isv + offV;
            double totalV = sm.b.dV[15];
            sm.b.prefExp[tid] = (float)(inclE - se);
            sm.b.sufVal[tid]  = (float)(totalV - (inclV - sv));
            if (tid == 0) {
                sm.b.sufVal[NB] = 0.0f;
                sm.b.totE = (float)sm.b.dE[15];
                sm.b.totV = (float)totalV;
            }
        }
    }
    __syncthreads();
    float totE = sm.b.totE, totV = sm.b.totV;

    // ===== fused queries + segment sum (16 threads per graph) =====
    {
        int gb = tid >> 4, q = tid & 15;
        int s = sm.b.segStart[gb], e = sm.b.segStart[gb + 1];
        float p = 0.0f;
        for (int n = s + q; n < e; n += 16) {
            float am = sm.b.qam[n], eam = sm.b.qem[n];
            float t = -am;
            float acc;
            if (t >= mxv) {                     // all elements on exp side (exact)
                acc = eam * totE;
            } else if (t < mnv) {               // all elements on linear side (exact)
                acc = fmaf((float)P_PRO, am + 1.0f, totV);
            } else {
                int b  = bin_of(t, mnv, inv);
                int s0 = sm.b.binStart[b], e0 = sm.b.binStart[b + 1];
                float cb  = (float)(e0 - s0);
                float sV  = sm.b.sumVb[b];
                float sV2 = sm.b.sumV2b[b];
                float lin = am + 1.0f;
                // bins<b exact exp side; bins>b exact linear side; boundary bin:
                // sum of 1 + x + x^2/4 with x = am+v, |x| <= ~2*binwidth
                acc = eam * sm.b.prefExp[b] + sm.b.sufVal[b + 1]
                    + (float)(P_PRO - e0) * lin
                    + cb * lin + sV
                    + 0.25f * fmaf(cb, am * am, fmaf(2.0f * am, sV, sV2));
            }
            p += acc;
        }
#pragma unroll
        for (int o = 8; o > 0; o >>= 1) p += __shfl_xor_sync(0xffffffffu, p, o);
        if (q == 0) g_ys[gb * HEADS + h] = p * 0.001f;
    }
    __threadfence();
    __syncthreads();

    // ===== last consumer to finish runs the MLP (zero spin) =====
    if (tid == 0) {
        int last = (atomicAdd(&g_done, 1) == HEADS - 1);
        if (last) {
            atomicExch(&g_done, 0);       // reset for next replay
            __threadfence();
        }
        sm.b.amLast = last;
    }
    __syncthreads();
    if (!sm.b.amLast) return;

    // all 15 other consumers have published g_ys (their fences precede their adds)
    float* ysF = sm.b.qam;    // dead; reuse for 64x16 ys
    if (tid < NGRAPH * HEADS) ysF[tid] = __ldcg(&g_ys[tid]);
    __syncthreads();
#pragma unroll
    for (int pass = 0; pass < 2; pass++) {
        int gb = (tid >> 5) + pass * 32;     // graph
        int j  = tid & 31;                   // hidden unit
        float a = b1[j];
#pragma unroll
        for (int hh = 0; hh < HEADS; hh++)
            a += ysF[gb * HEADS + hh] * sm.b.w1s[hh * (2 * HEADS) + j];
        float el = (a > 0.0f) ? a : (expf(a) - 1.0f);
        float c = el * W2[j];
#pragma unroll
        for (int o = 16; o > 0; o >>= 1) c += __shfl_xor_sync(0xffffffffu, c, o);
        if (j == 0) out[gb] = c + b2[0];
    }
}

// Inputs (metadata order):
// 0 mol_feats [2048,64] f32   1 fused_feats [2048,64] f32
// 2 Wmu [128,16] f32          3 bmu [16] f32
// 4 W1 [16,32] f32            5 b1 [32] f32
// 6 W2 [32,1] f32             7 b2 [1] f32
// 8 mol_batch [2048] int64-or-int32   9 num_graphs (static B=64)
extern "C" void kernel_launch(void* const* d_in, const int* in_sizes, int n_in,
                              void* d_out, int out_size) {
    fused_kernel<<<NBLK, NTHR>>>(
        (const float*)d_in[0], (const float*)d_in[1],
        (const float*)d_in[2], (const float*)d_in[3],
        (const float*)d_in[4], (const float*)d_in[5],
        (const float*)d_in[6], (const float*)d_in[7],
        (const int*)d_in[8], (float*)d_out);
}

// round 17
// speedup vs baseline: 1.1083x; 1.0135x over previous
#include <cuda_runtime.h>
#include <math.h>

#define N_MOL  2048
#define P_PRO  2048
#define HID    64
#define HEADS  16
#define NGRAPH 64
#define NB     512
#define NBLK   144          // 16 prep-only consumers + 128 producers
#define NTHR   1024
#define AROWS  32           // rows per producer block in Phase A

// ---- global scratch (no allocation allowed) ----
__device__ float2 g_mol2[HEADS][N_MOL];   // (a_mol, exp(a_mol))
__device__ float2 g_pro2[HEADS][P_PRO];   // (a_pro, exp(a_pro))
__device__ float  g_ys[NGRAPH * HEADS];
__device__ unsigned g_mnU[HEADS] = {      // order-encoded per-head min (consumers reset)
    0xFFFFFFFFu,0xFFFFFFFFu,0xFFFFFFFFu,0xFFFFFFFFu,0xFFFFFFFFu,0xFFFFFFFFu,
    0xFFFFFFFFu,0xFFFFFFFFu,0xFFFFFFFFu,0xFFFFFFFFu,0xFFFFFFFFu,0xFFFFFFFFu,
    0xFFFFFFFFu,0xFFFFFFFFu,0xFFFFFFFFu,0xFFFFFFFFu};
__device__ unsigned g_mxU[HEADS];         // zero-init = encoded far-below-min
__device__ int    g_gen;                  // barrier generation (monotone)
__device__ int    g_cnt1[18];             // leaf arrival counters (self-reset)
__device__ int    g_count;                // root arrival counter (self-resets)
__device__ int    g_done;                 // consumer completions (self-resets)

struct SA {                                // Phase A: 14,656 B
    float rows[AROWS * HID];               // 8192
    float Wst[HEADS][68];                  // 4352  transposed weights, padded rows
    float trans[HEADS][AROWS + 1];         // 2112
};
struct SB {                                // Phase B
    float2 VE[P_PRO];                      // 16384  (post-barrier)
    union { int bs[N_MOL];   float qam[N_MOL]; };  // bs pre-barrier -> qam post
    union { float dead[N_MOL]; float qem[N_MOL]; };
    int    segStart[NGRAPH + 1];           // pre-barrier segment boundaries
    int    hist[NB];                       // pre-barrier zeroed
    int    cnt[NB];                        // pre-barrier zeroed
    int    binStart[NB + 1];
    float  prefExp[NB];                    // sum e^v over bins < k
    float  sufVal[NB + 1];                 // sum v over bins >= k
    float  sumVb[NB];                      // per-bin sum of values
    float  sumV2b[NB];                     // per-bin sum of squares
    float  w1s[2 * HEADS * HEADS];         // W1 preload (pre-barrier)
    int    iwarp[16];
    double dE[16], dV[16];
    float  mnv, mxv, invv, totE, totV;
    int    flag;
    int    amLast;
};
union SmemU { SA a; SB b; };

// order-preserving float<->uint encoding (atomicMin/Max-compatible)
__device__ __forceinline__ unsigned encF(float f) {
    unsigned b = __float_as_uint(f);
    return (b & 0x80000000u) ? ~b : (b | 0x80000000u);
}
__device__ __forceinline__ float decF(unsigned u) {
    return (u & 0x80000000u) ? __uint_as_float(u & 0x7FFFFFFFu)
                             : __uint_as_float(~u);
}
__device__ __forceinline__ int bin_of(float v, float mn, float inv) {
    // single shared helper => identical rounding for elements and queries
    int b = (int)(__fmul_rn(__fsub_rn(v, mn), inv));
    return b < 0 ? 0 : (b > NB - 1 ? NB - 1 : b);
}
// two-level arrival: 18 leaves x 8, root x 18; last arriver bumps g_gen
__device__ __forceinline__ void barrier_arrive(int bid) {
    if (atomicAdd(&g_cnt1[bid >> 3], 1) == 7) {
        atomicExch(&g_cnt1[bid >> 3], 0);
        if (atomicAdd(&g_count, 1) == 17) {
            atomicExch(&g_count, 0);
            __threadfence();
            atomicAdd(&g_gen, 1);
        }
    }
}

__global__ __launch_bounds__(NTHR, 1)
void fused_kernel(const float* __restrict__ mol,
                  const float* __restrict__ pro,
                  const float* __restrict__ Wmu,
                  const float* __restrict__ bmu,
                  const float* __restrict__ W1,
                  const float* __restrict__ b1,
                  const float* __restrict__ W2,
                  const float* __restrict__ b2,
                  const int*   __restrict__ batch32,
                  float* __restrict__ out) {
    __shared__ SmemU sm;
    int tid  = threadIdx.x;
    int lane = tid & 31;
    int wrp  = tid >> 5;
    int bid  = blockIdx.x;

    // ================== producers: blocks 16..143 ==================
    if (bid >= HEADS) {
        int  grp     = bid - HEADS;          // 0..127
        bool is_mol  = grp < 64;
        int  rowbase = (grp & 63) * AROWS;
        const float* srcbase = is_mol ? mol : pro;
        {   // transposed weight fill: coalesced LDG, one STS per thread
            int k = tid >> 4, hh = tid & 15;
            sm.a.Wst[hh][k] = Wmu[(is_mol ? 0 : 1024) + tid];
        }
        if (tid < AROWS * HID / 4)
            ((float4*)sm.a.rows)[tid] = ((const float4*)(srcbase + rowbase * HID))[tid];
        __syncthreads();
        if (tid < AROWS * HEADS) {   // 512 products: warp = 2 rows x 16 heads
            int r = tid >> 4, h = tid & 15;
            const float4* rp = (const float4*)&sm.a.rows[r * HID];
            const float4* wp = (const float4*)&sm.a.Wst[h][0];
            float acc = is_mol ? bmu[h] : 0.0f;
#pragma unroll
            for (int q = 0; q < 16; q++) {
                float4 rv = rp[q];
                float4 wv = wp[q];
                acc += rv.x * wv.x; acc += rv.y * wv.y;
                acc += rv.z * wv.z; acc += rv.w * wv.w;
            }
            sm.a.trans[h][r] = acc;
        }
        __syncthreads();
        if (tid < AROWS * HEADS) {   // writeout: warp = one head x 32 rows, coalesced
            int h2 = tid >> 5, r2 = tid & 31;
            float a = sm.a.trans[h2][r2];
            float2* dst = is_mol ? g_mol2[h2] : g_pro2[h2];
            dst[rowbase + r2] = make_float2(a, __expf(a));
            if (!is_mol) {
                float wmn = a, wmx = a;
#pragma unroll
                for (int o = 16; o > 0; o >>= 1) {
                    wmn = fminf(wmn, __shfl_xor_sync(0xffffffffu, wmn, o));
                    wmx = fmaxf(wmx, __shfl_xor_sync(0xffffffffu, wmx, o));
                }
                if (lane == 0) {
                    atomicMin(&g_mnU[h2], encF(wmn));
                    atomicMax(&g_mxU[h2], encF(wmx));
                }
            }
        }
        __threadfence();
        __syncthreads();
        if (tid == 0) barrier_arrive(bid);
        return;
    }

    // ================== consumers: blocks 0..15 (prep-only, no Phase A) ==================
    int h = bid;
    int my = 0;
    if (tid == 0) {
        my = *(volatile int*)&g_gen;      // snapshot BEFORE our arrival => precedes bump
        barrier_arrive(bid);
    }

    // prep, fully overlapped with producers' Phase A
    for (int i = tid; i < N_MOL; i += NTHR) sm.b.bs[i] = batch32[i];
    if (tid < NB) { sm.b.hist[tid] = 0; sm.b.cnt[tid] = 0; }
    if (tid < 2 * HEADS * HEADS) sm.b.w1s[tid] = W1[tid];   // any consumer may finish last
    if (tid == 0) sm.b.flag = 0;
    __syncthreads();
    // int64 detection: sorted int32 word stream is monotone; int64's is not
    for (int i = tid; i < N_MOL - 1; i += NTHR)
        if (sm.b.bs[i] > sm.b.bs[i + 1]) sm.b.flag = 1;
    __syncthreads();
    if (sm.b.flag) {   // int64: low word of each element
        for (int i = tid; i < N_MOL; i += NTHR) sm.b.bs[i] = batch32[2 * i];
    }
    __syncthreads();
    // segment boundaries via binary search, OFF the post-barrier critical path
    if (tid <= NGRAPH) {
        int lo = 0, hi = N_MOL;
        while (lo < hi) { int m = (lo + hi) >> 1; if (sm.b.bs[m] < tid) lo = m + 1; else hi = m; }
        sm.b.segStart[tid] = lo;
    }
    __syncthreads();   // bs reads done before qam/qem overwrite below

    // ===== spin on barrier; tid0 also fetches producer min/max =====
    if (tid == 0) {
        while (*(volatile int*)&g_gen == my) {}
        __threadfence();
        float a = decF(*(volatile unsigned*)&g_mnU[h]);
        float b = decF(*(volatile unsigned*)&g_mxU[h]);
        g_mnU[h] = 0xFFFFFFFFu;           // reset for next replay
        g_mxU[h] = 0u;
        sm.b.mnv = a; sm.b.mxv = b;
        sm.b.invv = (b > a) ? (float)NB / (b - a) : 0.0f;
    }
    __syncthreads();
    float mnv = sm.b.mnv, mxv = sm.b.mxv, inv = sm.b.invv;

    // ===== Phase B: all global loads up front; mol2 staged to smem =====
    float2 pA = g_pro2[h][tid];
    float2 pB = g_pro2[h][tid + 1024];
    {
        float2 qA = g_mol2[h][tid];
        float2 qB = g_mol2[h][tid + 1024];
        sm.b.qam[tid] = qA.x;        sm.b.qem[tid] = qA.y;
        sm.b.qam[tid + 1024] = qB.x; sm.b.qem[tid + 1024] = qB.y;
    }

    // histogram straight from registers
    int bA = bin_of(pA.x, mnv, inv), bB = bin_of(pB.x, mnv, inv);
    atomicAdd(&sm.b.hist[bA], 1);
    atomicAdd(&sm.b.hist[bB], 1);
    __syncthreads();

    // exclusive scan of hist -> binStart (512 entries, 16 warps, shfl hierarchy)
    int myCnt = 0, myIncl = 0;
    {
        int s = 0;
        if (tid < NB) {
            myCnt = sm.b.hist[tid];
            s = myCnt;
#pragma unroll
            for (int o = 1; o < 32; o <<= 1) {
                int t = __shfl_up_sync(0xffffffffu, s, o);
                if (lane >= o) s += t;
            }
            if (lane == 31) sm.b.iwarp[wrp] = s;
        }
        __syncthreads();
        if (tid < 16) {
            int p = sm.b.iwarp[tid];
#pragma unroll
            for (int o = 1; o < 16; o <<= 1) {
                int t = __shfl_up_sync(0xffffu, p, o);
                if (tid >= o) p += t;
            }
            sm.b.iwarp[tid] = p;
        }
        __syncthreads();
        if (tid < NB) {
            myIncl = s + (wrp > 0 ? sm.b.iwarp[wrp - 1] : 0);
            sm.b.binStart[tid + 1] = myIncl;
            if (tid == 0) sm.b.binStart[0] = 0;
        }
    }
    __syncthreads();

    // scatter from registers
    {
        int pos = sm.b.binStart[bA] + atomicAdd(&sm.b.cnt[bA], 1);
        sm.b.VE[pos] = pA;
        pos = sm.b.binStart[bB] + atomicAdd(&sm.b.cnt[bB], 1);
        sm.b.VE[pos] = pB;
    }
    __syncthreads();

    // per-bin moments + joint double scan (prefExp exclusive / sufVal suffix)
    {
        double se = 0.0, sv = 0.0;
        if (tid < NB) {
            int s0 = myIncl - myCnt, e0 = myIncl;
            float fe = 0.0f, fv = 0.0f, fv2 = 0.0f;
            for (int i = s0; i < e0; i++) {
                float2 ve = sm.b.VE[i];
                fe += ve.y; fv += ve.x; fv2 += ve.x * ve.x;
            }
            sm.b.sumVb[tid]  = fv;
            sm.b.sumV2b[tid] = fv2;
            se = (double)fe; sv = (double)fv;
        }
        double ise = se, isv = sv;
        if (tid < NB) {
#pragma unroll
            for (int o = 1; o < 32; o <<= 1) {
                double te = __shfl_up_sync(0xffffffffu, ise, o);
                double tv = __shfl_up_sync(0xffffffffu, isv, o);
                if (lane >= o) { ise += te; isv += tv; }
            }
            if (lane == 31) { sm.b.dE[wrp] = ise; sm.b.dV[wrp] = isv; }
        }
        __syncthreads();
        if (tid < 16) {
            double pe = sm.b.dE[tid], pv = sm.b.dV[tid];
#pragma unroll
            for (int o = 1; o < 16; o <<= 1) {
                double te = __shfl_up_sync(0xffffu, pe, o);
                double tv = __shfl_up_sync(0xffffu, pv, o);
                if (tid >= o) { pe += te; pv += tv; }
            }
            sm.b.dE[tid] = pe; sm.b.dV[tid] = pv;
        }
        __syncthreads();
        if (tid < NB) {
            double offE = (wrp > 0) ? sm.b.dE[wrp - 1] : 0.0;
            double offV = (wrp > 0) ? sm.b.dV[wrp - 1] : 0.0;
            double inclE = ise + offE, inclV = isv + offV;
            double totalV = sm.b.dV[15];
            sm.b.prefExp[tid] = (float)(inclE - se);
            sm.b.sufVal[tid]  = (float)(totalV - (inclV - sv));
            if (tid == 0) {
                sm.b.sufVal[NB] = 0.0f;
                sm.b.totE = (float)sm.b.dE[15];
                sm.b.totV = (float)totalV;
            }
        }
    }
    __syncthreads();
    float totE = sm.b.totE, totV = sm.b.totV;

    // ===== fused queries + segment sum (16 threads per graph) =====
    {
        int gb = tid >> 4, q = tid & 15;
        int s = sm.b.segStart[gb], e = sm.b.segStart[gb + 1];
        float p = 0.0f;
        for (int n = s + q; n < e; n += 16) {
            float am = sm.b.qam[n], eam = sm.b.qem[n];
            float t = -am;
            float acc;
            if (t >= mxv) {                     // all elements on exp side (exact)
                acc = eam * totE;
            } else if (t < mnv) {               // all elements on linear side (exact)
                acc = fmaf((float)P_PRO, am + 1.0f, totV);
            } else {
                int b  = bin_of(t, mnv, inv);
                int s0 = sm.b.binStart[b], e0 = sm.b.binStart[b + 1];
                float cb  = (float)(e0 - s0);
                float sV  = sm.b.sumVb[b];
                float sV2 = sm.b.sumV2b[b];
                float lin = am + 1.0f;
                // bins<b exact exp side; bins>b exact linear side; boundary bin:
                // sum of 1 + x + x^2/4 with x = am+v, |x| <= ~2*binwidth
                acc = eam * sm.b.prefExp[b] + sm.b.sufVal[b + 1]
                    + (float)(P_PRO - e0) * lin
                    + cb * lin + sV
                    + 0.25f * fmaf(cb, am * am, fmaf(2.0f * am, sV, sV2));
            }
            p += acc;
        }
#pragma unroll
        for (int o = 8; o > 0; o >>= 1) p += __shfl_xor_sync(0xffffffffu, p, o);
        if (q == 0) g_ys[gb * HEADS + h] = p * 0.001f;
    }
    __threadfence();
    __syncthreads();

    // ===== last consumer to finish runs the MLP (zero spin) =====
    if (tid == 0) {
        int last = (atomicAdd(&g_done, 1) == HEADS - 1);
        if (last) {
            atomicExch(&g_done, 0);       // reset for next replay
            __threadfence();
        }
        sm.b.amLast = last;
    }
    __syncthreads();
    if (!sm.b.amLast) return;

    // all 15 other consumers have published g_ys (their fences precede their adds)
    float* ysF = sm.b.qam;    // dead; reuse for 64x16 ys
    if (tid < NGRAPH * HEADS) ysF[tid] = __ldcg(&g_ys[tid]);
    __syncthreads();
#pragma unroll
    for (int pass = 0; pass < 2; pass++) {
        int gb = (tid >> 5) + pass * 32;     // graph
        int j  = tid & 31;                   // hidden unit
        float a = b1[j];
#pragma unroll
        for (int hh = 0; hh < HEADS; hh++)
            a += ysF[gb * HEADS + hh] * sm.b.w1s[hh * (2 * HEADS) + j];
        float el = (a > 0.0f) ? a : (expf(a) - 1.0f);
        float c = el * W2[j];
#pragma unroll
        for (int o = 16; o > 0; o >>= 1) c += __shfl_xor_sync(0xffffffffu, c, o);
        if (j == 0) out[gb] = c + b2[0];
    }
}

// Inputs (metadata order):
// 0 mol_feats [2048,64] f32   1 fused_feats [2048,64] f32
// 2 Wmu [128,16] f32          3 bmu [16] f32
// 4 W1 [16,32] f32            5 b1 [32] f32
// 6 W2 [32,1] f32             7 b2 [1] f32
// 8 mol_batch [2048] int64-or-int32   9 num_graphs (static B=64)
extern "C" void kernel_launch(void* const* d_in, const int* in_sizes, int n_in,
                              void* d_out, int out_size) {
    fused_kernel<<<NBLK, NTHR>>>(
        (const float*)d_in[0], (const float*)d_in[1],
        (const float*)d_in[2], (const float*)d_in[3],
        (const float*)d_in[4], (const float*)d_in[5],
        (const float*)d_in[6], (const float*)d_in[7],
        (const int*)d_in[8], (float*)d_out);
}